// round 15
// baseline (speedup 1.0000x reference)
#include <cuda_runtime.h>
#include <cuda_fp16.h>
#include <cstdint>
#include <math.h>

#define BB 4
#define TT 4096
#define CC 1024
#define EE 8
#define KKK 2
#define HH 4096
#define NN (BB*TT)
#define CAP 8192

#define BM 128
#define BN 128
#define BK 64                               // k-depth per stage
#define STAGES 3
#define A_BYTES (BM*128)                    // 128 token-rows x 128B (64 halves)
#define B_BYTES (BK*256)                    // 64 k-rows x 256B (128 halves)
#define STAGE_BYTES (A_BYTES + B_BYTES)     // 32768
#define SMEM_BYTES (STAGES*STAGE_BYTES)     // 98304

// ---------------- device scratch ----------------
__device__ int    g_cnt[EE];
__device__ float  g_imp[EE];
__device__ int    g_rows[EE*CAP];
__device__ int    g_tokrow[NN*KKK];
__device__ float  g_tv[NN*KKK];
__device__ __half g_hh[(size_t)EE*CAP*HH];     // intermediate (fp16)
__device__ __half g_xh[(size_t)NN*CC];         // fp16 x (written by router)
__device__ __half g_w1h[(size_t)EE*CC*HH];     // fp16 w1, native [e][k=C][n=H]
__device__ __half g_w2h[(size_t)EE*HH*CC];     // fp16 w2, native [e][k=H][n=C]

__device__ __forceinline__ uint32_t pack_h2(float lo, float hi) {
    union { __half2 h; uint32_t u; } cv;
    cv.h = __floats2half2_rn(lo, hi);
    return cv.u;
}
__device__ __forceinline__ void cp16(uint32_t dst, const void* src) {
    asm volatile("cp.async.cg.shared.global [%0], [%1], 16;\n" :: "r"(dst), "l"(src));
}
__device__ __forceinline__ void cp_commit() {
    asm volatile("cp.async.commit_group;\n" ::: "memory");
}
template<int N> __device__ __forceinline__ void cp_wait() {
    asm volatile("cp.async.wait_group %0;\n" :: "n"(N) : "memory");
}
__device__ __forceinline__ void ldsm4(uint32_t& r0, uint32_t& r1, uint32_t& r2, uint32_t& r3,
                                      uint32_t addr) {
    asm volatile("ldmatrix.sync.aligned.m8n8.x4.shared.b16 {%0,%1,%2,%3}, [%4];"
        : "=r"(r0), "=r"(r1), "=r"(r2), "=r"(r3) : "r"(addr));
}
__device__ __forceinline__ void ldsm4t(uint32_t& r0, uint32_t& r1, uint32_t& r2, uint32_t& r3,
                                       uint32_t addr) {
    asm volatile("ldmatrix.sync.aligned.m8n8.x4.trans.shared.b16 {%0,%1,%2,%3}, [%4];"
        : "=r"(r0), "=r"(r1), "=r"(r2), "=r"(r3) : "r"(addr));
}

// ---------------- init ----------------
__global__ void init_k() {
    int i = threadIdx.x;
    if (i < EE) { g_cnt[i] = 0; g_imp[i] = 0.f; }
}

// ---------------- fp32 -> fp16 streaming convert (weights) ----------------
__global__ void cvt_h(const float4* __restrict__ src, uint4* __restrict__ dst, int n8) {
    int i = blockIdx.x * blockDim.x + threadIdx.x;
    if (i >= n8) return;
    float4 a = src[2*i], b = src[2*i+1];
    uint4 o;
    o.x = pack_h2(a.x, a.y);
    o.y = pack_h2(a.z, a.w);
    o.z = pack_h2(b.x, b.y);
    o.w = pack_h2(b.z, b.w);
    dst[i] = o;
}

// ---------------- router: rw staged in smem [c][8], float4 reads ------------
__global__ void router_k(const float* __restrict__ x,
                         const float* __restrict__ rw,
                         const float* __restrict__ rb) {
    __shared__ float srw[CC * 8];              // 32 KB
    __shared__ float simp[EE];
    __shared__ int   scnt[EE];
    __shared__ int   sbase[EE];
    __shared__ int   tok_e[8][2];
    __shared__ int   tok_lp[8][2];

    int tid  = threadIdx.x;
    int w    = tid >> 5;
    int lane = tid & 31;
    int gw   = blockIdx.x * 8 + w;

    if (tid < EE) { simp[tid] = 0.f; scnt[tid] = 0; }
    for (int idx = tid; idx < CC * EE; idx += 256) srw[idx] = rw[idx];
    __syncthreads();

    const float* xr = x + (size_t)gw * CC;
    __half* xh = g_xh + (size_t)gw * CC;

    float acc[EE];
#pragma unroll
    for (int e = 0; e < EE; e++) acc[e] = 0.f;

#pragma unroll 4
    for (int i = 0; i < CC/32; i++) {
        int c = i*32 + lane;
        float xv = xr[c];
        xh[c] = __float2half_rn(xv);
        const float4* wr = (const float4*)(srw + c * 8);
        float4 wa = wr[0], wb = wr[1];
        acc[0] = fmaf(xv, wa.x, acc[0]);
        acc[1] = fmaf(xv, wa.y, acc[1]);
        acc[2] = fmaf(xv, wa.z, acc[2]);
        acc[3] = fmaf(xv, wa.w, acc[3]);
        acc[4] = fmaf(xv, wb.x, acc[4]);
        acc[5] = fmaf(xv, wb.y, acc[5]);
        acc[6] = fmaf(xv, wb.z, acc[6]);
        acc[7] = fmaf(xv, wb.w, acc[7]);
    }
#pragma unroll
    for (int e = 0; e < EE; e++) {
#pragma unroll
        for (int off = 16; off; off >>= 1)
            acc[e] += __shfl_xor_sync(0xffffffffu, acc[e], off);
    }
    if (lane == 0) {
        float p[EE];
        float mx = -1e30f;
#pragma unroll
        for (int e = 0; e < EE; e++) { p[e] = acc[e] + rb[e]; mx = fmaxf(mx, p[e]); }
        float s = 0.f;
#pragma unroll
        for (int e = 0; e < EE; e++) { p[e] = expf(p[e] - mx); s += p[e]; }
        float inv = 1.f / s;
#pragma unroll
        for (int e = 0; e < EE; e++) p[e] *= inv;

        int i0 = 0;
#pragma unroll
        for (int e = 1; e < EE; e++) if (p[e] > p[i0]) i0 = e;
        int i1 = (i0 == 0) ? 1 : 0;
#pragma unroll
        for (int e = 0; e < EE; e++) if (e != i0 && p[e] > p[i1]) i1 = e;

        g_tv[gw*2]   = p[i0];
        g_tv[gw*2+1] = p[i1];
        int es[2] = { i0, i1 };
#pragma unroll
        for (int s2 = 0; s2 < 2; s2++) {
            int e = es[s2];
            tok_e[w][s2]  = e;
            tok_lp[w][s2] = atomicAdd(&scnt[e], 1);
        }
#pragma unroll
        for (int e = 0; e < EE; e++) atomicAdd(&simp[e], p[e]);
    }
    __syncthreads();
    if (tid < EE) {
        sbase[tid] = atomicAdd(&g_cnt[tid], scnt[tid]);
        atomicAdd(&g_imp[tid], simp[tid]);
    }
    __syncthreads();
    if (tid < 16) {
        int wt = tid >> 1, s2 = tid & 1;
        int e   = tok_e[wt][s2];
        int pos = sbase[e] + tok_lp[wt][s2];
        int gt  = blockIdx.x * 8 + wt;
        if (pos < CAP) {
            g_rows[e*CAP + pos]  = gt;
            g_tokrow[gt*2 + s2]  = e*CAP + pos;
        } else {
            g_tokrow[gt*2 + s2]  = -1;
        }
    }
}

// ---------------- grouped GEMM, fp16 m16n8k16, 4 warps of 64x64 -------------
// MODE 1: h = relu(gather(xh) @ w1[e] + b1[e])  -> fp16 (g_hh)
// MODE 2: out[tok] += w_tok * (h @ w2[e] + b2[e])   (atomic combine)
template<int MODE>
__global__ __launch_bounds__(128, 2)
void gemm_k(const float* __restrict__ bias, float* __restrict__ out) {
    constexpr int  Kdim  = (MODE == 1) ? CC : HH;
    constexpr int  outN  = (MODE == 1) ? HH : CC;
    constexpr int  ITERS = Kdim / BK;

    const __half* A = (MODE == 1) ? g_xh : g_hh;
    const __half* W = (MODE == 1) ? g_w1h : g_w2h;

    int e   = blockIdx.z;
    int cnt = min(g_cnt[e], CAP);
    int m0  = blockIdx.y * BM;
    if (m0 >= cnt) return;
    int n0  = blockIdx.x * BN;

    extern __shared__ char smem[];
    __shared__ int arow[BM];

    int tid  = threadIdx.x;
    int lane = tid & 31, warp = tid >> 5;

    {   // 128 threads cover BM rows exactly
        int idx = m0 + tid;
        if (MODE == 1) arow[tid] = (idx < cnt) ? g_rows[e*CAP + idx] : 0;
        else           arow[tid] = (idx < cnt) ? g_rows[e*CAP + idx] : -1;
    }
    __syncthreads();

    // ---- cp.async descriptors: 8 A + 8 B chunks per thread (16B) ----
    int j  = tid & 7;
    int rT = tid >> 3;                 // 0..15
    uint32_t adst0 = (uint32_t)(rT*128 + ((j ^ (rT & 7)) << 4));
    const __half* Aj = A + j*8;
    int j2 = tid & 15;
    int rB = tid >> 4;                 // 0..7
    uint32_t bdst0 = (uint32_t)(A_BYTES + rB*256 + ((j2 ^ (rB & 7)) << 4));
    const __half* Bj = W + (size_t)e * Kdim * outN + n0 + j2*8;

    uint32_t smbase = (uint32_t)__cvta_generic_to_shared(smem);

    auto issue = [&](int stage, int it) {
        uint32_t s = smbase + (uint32_t)stage * STAGE_BYTES;
        size_t koff = (size_t)it * BK;
#pragma unroll
        for (int i = 0; i < 8; i++) {
            int r = rT + 16*i;
            size_t ar = (MODE == 1) ? (size_t)arow[r] : (size_t)(e*CAP + m0 + r);
            cp16(s + adst0 + (uint32_t)i*2048, Aj + ar * Kdim + koff);
        }
#pragma unroll
        for (int i = 0; i < 8; i++)
            cp16(s + bdst0 + (uint32_t)i*2048, Bj + (koff + (size_t)(rB + 8*i)) * outN);
    };

    issue(0, 0); cp_commit();
    issue(1, 1); cp_commit();

    // ---- ldmatrix per-lane components (warp tile 64x64) ----
    int wm  = (warp & 1) * 64;
    int wn  = (warp >> 1) * 64;
    int r16 = lane & 15;
    int coff = lane >> 4;
    int sl7  = lane & 7;
    uint32_t aoff0 = (uint32_t)((wm + r16) * 128);
    int sub = lane & 7;
    int mi  = lane >> 3;
    int kl  = ((mi >> 1) << 3) + sub;     // 0..15
    int slotbit = mi & 1;
    uint32_t bsl[4];
#pragma unroll
    for (int p = 0; p < 4; p++) {
        int slot = (wn >> 3) + 2*p + slotbit;
        bsl[p] = (uint32_t)(A_BYTES + kl*256 + ((slot ^ sub) << 4));
    }

    float acc[4][8][4];
#pragma unroll
    for (int mt = 0; mt < 4; mt++)
#pragma unroll
        for (int nt = 0; nt < 8; nt++)
#pragma unroll
            for (int q = 0; q < 4; q++) acc[mt][nt][q] = 0.f;

    for (int it = 0; it < ITERS; ++it) {
        cp_wait<1>();
        __syncthreads();
        if (it + 2 < ITERS) issue((it + 2) % STAGES, it + 2);
        cp_commit();

        uint32_t stg = smbase + (uint32_t)(it % STAGES) * STAGE_BYTES;

#pragma unroll
        for (int ks = 0; ks < BK; ks += 16) {
            const int c0 = (ks >> 3) + coff;
            const uint32_t csw = (uint32_t)((c0 ^ sl7) << 4);
            uint32_t af[4][4], bf[8][2];
#pragma unroll
            for (int mt = 0; mt < 4; mt++)
                ldsm4(af[mt][0], af[mt][1], af[mt][2], af[mt][3],
                      stg + aoff0 + (uint32_t)mt*2048 + csw);
#pragma unroll
            for (int p = 0; p < 4; p++)
                ldsm4t(bf[2*p][0], bf[2*p+1][0], bf[2*p][1], bf[2*p+1][1],
                       stg + bsl[p] + (uint32_t)(ks << 8));
#pragma unroll
            for (int mt = 0; mt < 4; mt++)
#pragma unroll
                for (int nt = 0; nt < 8; nt++) {
                    asm volatile(
                        "mma.sync.aligned.m16n8k16.row.col.f32.f16.f16.f32 "
                        "{%0,%1,%2,%3}, {%4,%5,%6,%7}, {%8,%9}, {%0,%1,%2,%3};"
                        : "+f"(acc[mt][nt][0]), "+f"(acc[mt][nt][1]),
                          "+f"(acc[mt][nt][2]), "+f"(acc[mt][nt][3])
                        : "r"(af[mt][0]), "r"(af[mt][1]), "r"(af[mt][2]), "r"(af[mt][3]),
                          "r"(bf[nt][0]), "r"(bf[nt][1]));
                }
        }
    }

    // ---- epilogue ----
    int q  = lane & 3;
    int gg = lane >> 2;
#pragma unroll
    for (int mt = 0; mt < 4; mt++) {
        int mrow = wm + mt*16 + gg;
        int t0 = arow[mrow], t1 = arow[mrow + 8];
        float w0 = 0.f, w1v = 0.f;
        if (MODE == 2) {
            w0  = (t0 >= 0) ? g_tv[t0] : 0.f;
            w1v = (t1 >= 0) ? g_tv[t1] : 0.f;
        }
#pragma unroll
        for (int nt = 0; nt < 8; nt++) {
            int col  = n0 + wn + nt*8 + 2*q;
            float bc0 = bias[e * outN + col];
            float bc1 = bias[e * outN + col + 1];
            float v00 = acc[mt][nt][0] + bc0;
            float v01 = acc[mt][nt][1] + bc1;
            float v10 = acc[mt][nt][2] + bc0;
            float v11 = acc[mt][nt][3] + bc1;
            if (MODE == 1) {
                size_t o0 = ((size_t)(e * CAP + m0 + mrow)) * outN + col;
                size_t o1 = o0 + (size_t)8 * outN;
                *(uint32_t*)(g_hh + o0) = pack_h2(fmaxf(v00, 0.f), fmaxf(v01, 0.f));
                *(uint32_t*)(g_hh + o1) = pack_h2(fmaxf(v10, 0.f), fmaxf(v11, 0.f));
            } else {
                if (t0 >= 0) {
                    float* p0 = out + (size_t)t0 * CC + col;
                    atomicAdd(p0,     w0 * v00);
                    atomicAdd(p0 + 1, w0 * v01);
                }
                if (t1 >= 0) {
                    float* p1 = out + (size_t)t1 * CC + col;
                    atomicAdd(p1,     w1v * v10);
                    atomicAdd(p1 + 1, w1v * v11);
                }
            }
        }
    }
}

// ---------------- aux loss ----------------
__global__ void aux_k(float* __restrict__ out, int out_size) {
    int lane = threadIdx.x;
    float v = 0.f;
    if (lane < EE)
        v = (g_imp[lane] / (float)NN) * ((float)g_cnt[lane] / (float)(NN * KKK));
#pragma unroll
    for (int off = 16; off; off >>= 1) v += __shfl_xor_sync(0xffffffffu, v, off);
    if (lane == 0) {
        if (out_size > NN * CC)     out[(size_t)NN * CC] = v;
        if (out_size - 1 > NN * CC) out[(size_t)out_size - 1] = v;
    }
}

// ---------------- launch ----------------
extern "C" void kernel_launch(void* const* d_in, const int* in_sizes, int n_in,
                              void* d_out, int out_size) {
    const float* x  = (const float*)d_in[0];
    const float* rw = (const float*)d_in[1];
    const float* rb = (const float*)d_in[2];
    const float* w1 = (const float*)d_in[3];
    const float* b1 = (const float*)d_in[4];
    const float* w2 = (const float*)d_in[5];
    const float* b2 = (const float*)d_in[6];
    float* out = (float*)d_out;

    static cudaStream_t s2 = nullptr;
    static cudaEvent_t evStart = nullptr, evW1 = nullptr, evW2 = nullptr;
    if (!s2) {
        cudaStreamCreateWithFlags(&s2, cudaStreamNonBlocking);
        cudaEventCreateWithFlags(&evStart, cudaEventDisableTiming);
        cudaEventCreateWithFlags(&evW1,   cudaEventDisableTiming);
        cudaEventCreateWithFlags(&evW2,   cudaEventDisableTiming);
    }

    cudaFuncSetAttribute(gemm_k<1>, cudaFuncAttributeMaxDynamicSharedMemorySize, SMEM_BYTES);
    cudaFuncSetAttribute(gemm_k<2>, cudaFuncAttributeMaxDynamicSharedMemorySize, SMEM_BYTES);

    __half* w1h; cudaGetSymbolAddress((void**)&w1h, g_w1h);
    __half* w2h; cudaGetSymbolAddress((void**)&w2h, g_w2h);

    // fork s2 off the (captured) main stream
    cudaEventRecord(evStart, 0);
    cudaStreamWaitEvent(s2, evStart, 0);

    // s2: weight conversions + output zeroing (overlaps router/gemm1)
    {
        int n8 = (int)((size_t)EE * CC * HH / 8);
        cvt_h<<<(n8 + 255) / 256, 256, 0, s2>>>((const float4*)w1, (uint4*)w1h, n8);
        cudaEventRecord(evW1, s2);
        cvt_h<<<(n8 + 255) / 256, 256, 0, s2>>>((const float4*)w2, (uint4*)w2h, n8);
        cudaMemsetAsync(d_out, 0, (size_t)out_size * sizeof(float), s2);
        cudaEventRecord(evW2, s2);
    }

    // main: router (+x->fp16)
    init_k<<<1, 32>>>();
    router_k<<<NN / 8, 256>>>(x, rw, rb);

    // gemm1 needs router + w1h
    cudaStreamWaitEvent(0, evW1, 0);
    gemm_k<1><<<dim3(HH / BN, CAP / BM, EE), 128, SMEM_BYTES>>>(b1, nullptr);
    // gemm2 additionally needs w2h + zeroed out
    cudaStreamWaitEvent(0, evW2, 0);
    aux_k<<<1, 32>>>(out, out_size);
    gemm_k<2><<<dim3(CC / BN, CAP / BM, EE), 128, SMEM_BYTES>>>(b2, out);
}

// round 16
// speedup vs baseline: 1.0327x; 1.0327x over previous
#include <cuda_runtime.h>
#include <cuda_fp16.h>
#include <cstdint>
#include <math.h>

#define BB 4
#define TT 4096
#define CC 1024
#define EE 8
#define KKK 2
#define HH 4096
#define NN (BB*TT)
#define CAP 8192

#define BM 128
#define BN 128
#define BK 64                               // k-depth per stage
#define STAGES 3
#define A_BYTES (BM*128)                    // 128 token-rows x 128B (64 halves)
#define B_BYTES (BK*256)                    // 64 k-rows x 256B (128 halves)
#define STAGE_BYTES (A_BYTES + B_BYTES)     // 32768
#define SMEM_BYTES (STAGES*STAGE_BYTES)     // 98304

// ---------------- device scratch ----------------
__device__ int    g_cnt[EE];
__device__ float  g_imp[EE];
__device__ int    g_rows[EE*CAP];
__device__ int    g_tokrow[NN*KKK];
__device__ float  g_tv[NN*KKK];
__device__ __half g_hh[(size_t)EE*CAP*HH];     // intermediate (fp16)
__device__ __half g_xh[(size_t)NN*CC];         // fp16 x (written by router)
__device__ __half g_w1h[(size_t)EE*CC*HH];     // fp16 w1, native [e][k=C][n=H]
__device__ __half g_w2h[(size_t)EE*HH*CC];     // fp16 w2, native [e][k=H][n=C]

__device__ __forceinline__ uint32_t pack_h2(float lo, float hi) {
    union { __half2 h; uint32_t u; } cv;
    cv.h = __floats2half2_rn(lo, hi);
    return cv.u;
}
__device__ __forceinline__ void cp16(uint32_t dst, const void* src) {
    asm volatile("cp.async.cg.shared.global [%0], [%1], 16;\n" :: "r"(dst), "l"(src));
}
__device__ __forceinline__ void cp_commit() {
    asm volatile("cp.async.commit_group;\n" ::: "memory");
}
template<int N> __device__ __forceinline__ void cp_wait() {
    asm volatile("cp.async.wait_group %0;\n" :: "n"(N) : "memory");
}
__device__ __forceinline__ void ldsm4(uint32_t& r0, uint32_t& r1, uint32_t& r2, uint32_t& r3,
                                      uint32_t addr) {
    asm volatile("ldmatrix.sync.aligned.m8n8.x4.shared.b16 {%0,%1,%2,%3}, [%4];"
        : "=r"(r0), "=r"(r1), "=r"(r2), "=r"(r3) : "r"(addr));
}
__device__ __forceinline__ void ldsm4t(uint32_t& r0, uint32_t& r1, uint32_t& r2, uint32_t& r3,
                                       uint32_t addr) {
    asm volatile("ldmatrix.sync.aligned.m8n8.x4.trans.shared.b16 {%0,%1,%2,%3}, [%4];"
        : "=r"(r0), "=r"(r1), "=r"(r2), "=r"(r3) : "r"(addr));
}

// ---------------- init ----------------
__global__ void init_k() {
    int i = threadIdx.x;
    if (i < EE) { g_cnt[i] = 0; g_imp[i] = 0.f; }
}

// ---------------- fp32 -> fp16 streaming convert (weights) ----------------
__global__ void cvt_h(const float4* __restrict__ src, uint4* __restrict__ dst, int n8) {
    int i = blockIdx.x * blockDim.x + threadIdx.x;
    if (i >= n8) return;
    float4 a = src[2*i], b = src[2*i+1];
    uint4 o;
    o.x = pack_h2(a.x, a.y);
    o.y = pack_h2(a.z, a.w);
    o.z = pack_h2(b.x, b.y);
    o.w = pack_h2(b.z, b.w);
    dst[i] = o;
}

// ---------------- router: rw staged in smem (pitch 9 = conflict-free) -------
__global__ void router_k(const float* __restrict__ x,
                         const float* __restrict__ rw,
                         const float* __restrict__ rb) {
    __shared__ float srw[CC * 9];              // srw[c*9 + e], 36 KB
    __shared__ float simp[EE];
    __shared__ int   scnt[EE];
    __shared__ int   sbase[EE];
    __shared__ int   tok_e[8][2];
    __shared__ int   tok_lp[8][2];

    int tid  = threadIdx.x;
    int w    = tid >> 5;
    int lane = tid & 31;
    int gw   = blockIdx.x * 8 + w;

    if (tid < EE) { simp[tid] = 0.f; scnt[tid] = 0; }
    for (int idx = tid; idx < CC * EE; idx += 256) {
        int c = idx >> 3, e = idx & 7;
        srw[c * 9 + e] = rw[idx];
    }
    __syncthreads();

    const float* xr = x + (size_t)gw * CC;
    __half* xh = g_xh + (size_t)gw * CC;

    float acc[EE];
#pragma unroll
    for (int e = 0; e < EE; e++) acc[e] = 0.f;

#pragma unroll 4
    for (int i = 0; i < CC/32; i++) {
        int c = i*32 + lane;
        float xv = xr[c];
        xh[c] = __float2half_rn(xv);
        const float* wr = &srw[c * 9];
#pragma unroll
        for (int e = 0; e < EE; e++) acc[e] = fmaf(xv, wr[e], acc[e]);
    }
#pragma unroll
    for (int e = 0; e < EE; e++) {
#pragma unroll
        for (int off = 16; off; off >>= 1)
            acc[e] += __shfl_xor_sync(0xffffffffu, acc[e], off);
    }
    if (lane == 0) {
        float p[EE];
        float mx = -1e30f;
#pragma unroll
        for (int e = 0; e < EE; e++) { p[e] = acc[e] + rb[e]; mx = fmaxf(mx, p[e]); }
        float s = 0.f;
#pragma unroll
        for (int e = 0; e < EE; e++) { p[e] = expf(p[e] - mx); s += p[e]; }
        float inv = 1.f / s;
#pragma unroll
        for (int e = 0; e < EE; e++) p[e] *= inv;

        int i0 = 0;
#pragma unroll
        for (int e = 1; e < EE; e++) if (p[e] > p[i0]) i0 = e;
        int i1 = (i0 == 0) ? 1 : 0;
#pragma unroll
        for (int e = 0; e < EE; e++) if (e != i0 && p[e] > p[i1]) i1 = e;

        g_tv[gw*2]   = p[i0];
        g_tv[gw*2+1] = p[i1];
        int es[2] = { i0, i1 };
#pragma unroll
        for (int s2 = 0; s2 < 2; s2++) {
            int e = es[s2];
            tok_e[w][s2]  = e;
            tok_lp[w][s2] = atomicAdd(&scnt[e], 1);
        }
#pragma unroll
        for (int e = 0; e < EE; e++) atomicAdd(&simp[e], p[e]);
    }
    __syncthreads();
    if (tid < EE) {
        sbase[tid] = atomicAdd(&g_cnt[tid], scnt[tid]);
        atomicAdd(&g_imp[tid], simp[tid]);
    }
    __syncthreads();
    if (tid < 16) {
        int wt = tid >> 1, s2 = tid & 1;
        int e   = tok_e[wt][s2];
        int pos = sbase[e] + tok_lp[wt][s2];
        int gt  = blockIdx.x * 8 + wt;
        if (pos < CAP) {
            g_rows[e*CAP + pos]  = gt;
            g_tokrow[gt*2 + s2]  = e*CAP + pos;
        } else {
            g_tokrow[gt*2 + s2]  = -1;
        }
    }
}

// ---------------- grouped GEMM, fp16 m16n8k16, 8 warps of 32x64 -------------
// MODE 1: h = relu(gather(xh) @ w1[e] + b1[e])  -> fp16 (g_hh)
// MODE 2: out[tok] += w_tok * (h @ w2[e] + b2[e])   (atomic combine)
template<int MODE>
__global__ __launch_bounds__(256, 2)
void gemm_k(const float* __restrict__ bias, float* __restrict__ out) {
    constexpr int  Kdim  = (MODE == 1) ? CC : HH;
    constexpr int  outN  = (MODE == 1) ? HH : CC;
    constexpr int  ITERS = Kdim / BK;

    const __half* A = (MODE == 1) ? g_xh : g_hh;
    const __half* W = (MODE == 1) ? g_w1h : g_w2h;

    int e   = blockIdx.z;
    int cnt = min(g_cnt[e], CAP);
    int m0  = blockIdx.y * BM;
    if (m0 >= cnt) return;
    int n0  = blockIdx.x * BN;

    extern __shared__ char smem[];
    __shared__ int arow[BM];

    int tid  = threadIdx.x;
    int lane = tid & 31, warp = tid >> 5;

    if (tid < BM) {
        int idx = m0 + tid;
        if (MODE == 1) arow[tid] = (idx < cnt) ? g_rows[e*CAP + idx] : 0;
        else           arow[tid] = (idx < cnt) ? g_rows[e*CAP + idx] : -1;
    }
    __syncthreads();

    // ---- cp.async descriptors ----
    int j  = tid & 7;
    int rT = tid >> 3;                 // 0..31
    uint32_t adst0 = (uint32_t)(rT*128 + ((j ^ (rT & 7)) << 4));
    const __half* Aj = A + j*8;
    int j2 = tid & 15;
    int rB = tid >> 4;                 // 0..15
    uint32_t bdst0 = (uint32_t)(A_BYTES + rB*256 + ((j2 ^ (rB & 7)) << 4));
    const __half* Bj = W + (size_t)e * Kdim * outN + n0 + j2*8;

    uint32_t smbase = (uint32_t)__cvta_generic_to_shared(smem);

    auto issue = [&](int stage, int it) {
        uint32_t s = smbase + (uint32_t)stage * STAGE_BYTES;
        size_t koff = (size_t)it * BK;
#pragma unroll
        for (int i = 0; i < 4; i++) {
            int r = rT + 32*i;
            size_t ar = (MODE == 1) ? (size_t)arow[r] : (size_t)(e*CAP + m0 + r);
            cp16(s + adst0 + (uint32_t)i*4096, Aj + ar * Kdim + koff);
        }
#pragma unroll
        for (int i = 0; i < 4; i++)
            cp16(s + bdst0 + (uint32_t)i*4096, Bj + (koff + (size_t)(rB + 16*i)) * outN);
    };

    issue(0, 0); cp_commit();
    issue(1, 1); cp_commit();

    // ---- ldmatrix per-lane components ----
    int wm  = (warp & 3) * 32;
    int wn  = (warp >> 2) * 64;
    int r16 = lane & 15;
    int coff = lane >> 4;
    int sl7  = lane & 7;
    uint32_t aoff0 = (uint32_t)((wm + r16) * 128);
    int sub = lane & 7;
    int mi  = lane >> 3;
    int kl  = ((mi >> 1) << 3) + sub;     // 0..15
    int slotbit = mi & 1;
    uint32_t bsl[4];
#pragma unroll
    for (int p = 0; p < 4; p++) {
        int slot = (wn >> 3) + 2*p + slotbit;
        bsl[p] = (uint32_t)(A_BYTES + kl*256 + ((slot ^ sub) << 4));
    }

    float acc[2][8][4];
#pragma unroll
    for (int mt = 0; mt < 2; mt++)
#pragma unroll
        for (int nt = 0; nt < 8; nt++)
#pragma unroll
            for (int q = 0; q < 4; q++) acc[mt][nt][q] = 0.f;

    for (int it = 0; it < ITERS; ++it) {
        cp_wait<1>();
        __syncthreads();
        if (it + 2 < ITERS) issue((it + 2) % STAGES, it + 2);
        cp_commit();

        uint32_t stg = smbase + (uint32_t)(it % STAGES) * STAGE_BYTES;

#pragma unroll
        for (int ks = 0; ks < BK; ks += 16) {
            const int c0 = (ks >> 3) + coff;
            const uint32_t csw = (uint32_t)((c0 ^ sl7) << 4);
            uint32_t af[2][4], bf[8][2];
#pragma unroll
            for (int mt = 0; mt < 2; mt++)
                ldsm4(af[mt][0], af[mt][1], af[mt][2], af[mt][3],
                      stg + aoff0 + (uint32_t)mt*2048 + csw);
#pragma unroll
            for (int p = 0; p < 4; p++)
                ldsm4t(bf[2*p][0], bf[2*p+1][0], bf[2*p][1], bf[2*p+1][1],
                       stg + bsl[p] + (uint32_t)(ks << 8));
#pragma unroll
            for (int mt = 0; mt < 2; mt++)
#pragma unroll
                for (int nt = 0; nt < 8; nt++) {
                    asm volatile(
                        "mma.sync.aligned.m16n8k16.row.col.f32.f16.f16.f32 "
                        "{%0,%1,%2,%3}, {%4,%5,%6,%7}, {%8,%9}, {%0,%1,%2,%3};"
                        : "+f"(acc[mt][nt][0]), "+f"(acc[mt][nt][1]),
                          "+f"(acc[mt][nt][2]), "+f"(acc[mt][nt][3])
                        : "r"(af[mt][0]), "r"(af[mt][1]), "r"(af[mt][2]), "r"(af[mt][3]),
                          "r"(bf[nt][0]), "r"(bf[nt][1]));
                }
        }
    }

    // ---- epilogue ----
    int q  = lane & 3;
    int gg = lane >> 2;
#pragma unroll
    for (int mt = 0; mt < 2; mt++) {
        int mrow = wm + mt*16 + gg;
        int t0 = arow[mrow], t1 = arow[mrow + 8];
        float w0 = 0.f, w1v = 0.f;
        if (MODE == 2) {
            w0  = (t0 >= 0) ? g_tv[t0] : 0.f;
            w1v = (t1 >= 0) ? g_tv[t1] : 0.f;
        }
#pragma unroll
        for (int nt = 0; nt < 8; nt++) {
            int col  = n0 + wn + nt*8 + 2*q;
            float bc0 = bias[e * outN + col];
            float bc1 = bias[e * outN + col + 1];
            float v00 = acc[mt][nt][0] + bc0;
            float v01 = acc[mt][nt][1] + bc1;
            float v10 = acc[mt][nt][2] + bc0;
            float v11 = acc[mt][nt][3] + bc1;
            if (MODE == 1) {
                size_t o0 = ((size_t)(e * CAP + m0 + mrow)) * outN + col;
                size_t o1 = o0 + (size_t)8 * outN;
                *(uint32_t*)(g_hh + o0) = pack_h2(fmaxf(v00, 0.f), fmaxf(v01, 0.f));
                *(uint32_t*)(g_hh + o1) = pack_h2(fmaxf(v10, 0.f), fmaxf(v11, 0.f));
            } else {
                if (t0 >= 0) {
                    float* p0 = out + (size_t)t0 * CC + col;
                    atomicAdd(p0,     w0 * v00);
                    atomicAdd(p0 + 1, w0 * v01);
                }
                if (t1 >= 0) {
                    float* p1 = out + (size_t)t1 * CC + col;
                    atomicAdd(p1,     w1v * v10);
                    atomicAdd(p1 + 1, w1v * v11);
                }
            }
        }
    }
}

// ---------------- aux loss ----------------
__global__ void aux_k(float* __restrict__ out, int out_size) {
    int lane = threadIdx.x;
    float v = 0.f;
    if (lane < EE)
        v = (g_imp[lane] / (float)NN) * ((float)g_cnt[lane] / (float)(NN * KKK));
#pragma unroll
    for (int off = 16; off; off >>= 1) v += __shfl_xor_sync(0xffffffffu, v, off);
    if (lane == 0) {
        if (out_size > NN * CC)     out[(size_t)NN * CC] = v;
        if (out_size - 1 > NN * CC) out[(size_t)out_size - 1] = v;
    }
}

// ---------------- launch ----------------
extern "C" void kernel_launch(void* const* d_in, const int* in_sizes, int n_in,
                              void* d_out, int out_size) {
    const float* x  = (const float*)d_in[0];
    const float* rw = (const float*)d_in[1];
    const float* rb = (const float*)d_in[2];
    const float* w1 = (const float*)d_in[3];
    const float* b1 = (const float*)d_in[4];
    const float* w2 = (const float*)d_in[5];
    const float* b2 = (const float*)d_in[6];
    float* out = (float*)d_out;

    static cudaStream_t s2 = nullptr;
    static cudaEvent_t evStart = nullptr, evW1 = nullptr, evW2 = nullptr;
    if (!s2) {
        cudaStreamCreateWithFlags(&s2, cudaStreamNonBlocking);
        cudaEventCreateWithFlags(&evStart, cudaEventDisableTiming);
        cudaEventCreateWithFlags(&evW1,   cudaEventDisableTiming);
        cudaEventCreateWithFlags(&evW2,   cudaEventDisableTiming);
    }

    cudaFuncSetAttribute(gemm_k<1>, cudaFuncAttributeMaxDynamicSharedMemorySize, SMEM_BYTES);
    cudaFuncSetAttribute(gemm_k<2>, cudaFuncAttributeMaxDynamicSharedMemorySize, SMEM_BYTES);

    __half* w1h; cudaGetSymbolAddress((void**)&w1h, g_w1h);
    __half* w2h; cudaGetSymbolAddress((void**)&w2h, g_w2h);

    // fork s2 off the (captured) main stream
    cudaEventRecord(evStart, 0);
    cudaStreamWaitEvent(s2, evStart, 0);

    // s2: weight conversions + output zeroing (overlaps router/gemm1)
    {
        int n8 = (int)((size_t)EE * CC * HH / 8);
        cvt_h<<<(n8 + 255) / 256, 256, 0, s2>>>((const float4*)w1, (uint4*)w1h, n8);
        cudaEventRecord(evW1, s2);
        cvt_h<<<(n8 + 255) / 256, 256, 0, s2>>>((const float4*)w2, (uint4*)w2h, n8);
        cudaMemsetAsync(d_out, 0, (size_t)out_size * sizeof(float), s2);
        cudaEventRecord(evW2, s2);
    }

    // main: router (+x->fp16)
    init_k<<<1, 32>>>();
    router_k<<<NN / 8, 256>>>(x, rw, rb);

    // gemm1 needs router + w1h
    cudaStreamWaitEvent(0, evW1, 0);
    gemm_k<1><<<dim3(HH / BN, CAP / BM, EE), 256, SMEM_BYTES>>>(b1, nullptr);
    // gemm2 additionally needs w2h + zeroed out
    cudaStreamWaitEvent(0, evW2, 0);
    aux_k<<<1, 32>>>(out, out_size);
    gemm_k<2><<<dim3(CC / BN, CAP / BM, EE), 256, SMEM_BYTES>>>(b2, out);
}

// round 17
// speedup vs baseline: 1.0397x; 1.0068x over previous
#include <cuda_runtime.h>
#include <cuda_fp16.h>
#include <cstdint>
#include <math.h>

#define BB 4
#define TT 4096
#define CC 1024
#define EE 8
#define KKK 2
#define HH 4096
#define NN (BB*TT)
#define CAP 8192
#define YTILES 48                           // y-grid tiles (cap 6144 rows/expert)

#define BM 128
#define BN 128
#define BK 64                               // k-depth per stage
#define STAGES 3
#define A_BYTES (BM*128)                    // 128 token-rows x 128B (64 halves)
#define B_BYTES (BK*256)                    // 64 k-rows x 256B (128 halves)
#define STAGE_BYTES (A_BYTES + B_BYTES)     // 32768
#define SMEM_BYTES (STAGES*STAGE_BYTES)     // 98304

// ---------------- device scratch ----------------
__device__ int    g_cnt[EE];
__device__ float  g_imp[EE];
__device__ int    g_rows[EE*CAP];
__device__ int    g_tokrow[NN*KKK];
__device__ float  g_tv[NN*KKK];
__device__ __half g_hh[(size_t)EE*CAP*HH];     // intermediate (fp16)
__device__ __half g_xh[(size_t)NN*CC];         // fp16 x (written by router)
__device__ __half g_w1h[(size_t)EE*CC*HH];     // fp16 w1, native [e][k=C][n=H]
__device__ __half g_w2h[(size_t)EE*HH*CC];     // fp16 w2, native [e][k=H][n=C]

__device__ __forceinline__ uint32_t pack_h2(float lo, float hi) {
    union { __half2 h; uint32_t u; } cv;
    cv.h = __floats2half2_rn(lo, hi);
    return cv.u;
}
__device__ __forceinline__ void cp16(uint32_t dst, const void* src) {
    asm volatile("cp.async.cg.shared.global [%0], [%1], 16;\n" :: "r"(dst), "l"(src));
}
__device__ __forceinline__ void cp_commit() {
    asm volatile("cp.async.commit_group;\n" ::: "memory");
}
template<int N> __device__ __forceinline__ void cp_wait() {
    asm volatile("cp.async.wait_group %0;\n" :: "n"(N) : "memory");
}
__device__ __forceinline__ void ldsm4(uint32_t& r0, uint32_t& r1, uint32_t& r2, uint32_t& r3,
                                      uint32_t addr) {
    asm volatile("ldmatrix.sync.aligned.m8n8.x4.shared.b16 {%0,%1,%2,%3}, [%4];"
        : "=r"(r0), "=r"(r1), "=r"(r2), "=r"(r3) : "r"(addr));
}
__device__ __forceinline__ void ldsm4t(uint32_t& r0, uint32_t& r1, uint32_t& r2, uint32_t& r3,
                                       uint32_t addr) {
    asm volatile("ldmatrix.sync.aligned.m8n8.x4.trans.shared.b16 {%0,%1,%2,%3}, [%4];"
        : "=r"(r0), "=r"(r1), "=r"(r2), "=r"(r3) : "r"(addr));
}

// ---------------- init ----------------
__global__ void init_k() {
    int i = threadIdx.x;
    if (i < EE) { g_cnt[i] = 0; g_imp[i] = 0.f; }
}

// ---------------- fp32 -> fp16 streaming convert (weights) ----------------
__global__ void cvt_h(const float4* __restrict__ src, uint4* __restrict__ dst, int n8) {
    int i = blockIdx.x * blockDim.x + threadIdx.x;
    if (i >= n8) return;
    float4 a = src[2*i], b = src[2*i+1];
    uint4 o;
    o.x = pack_h2(a.x, a.y);
    o.y = pack_h2(a.z, a.w);
    o.z = pack_h2(b.x, b.y);
    o.w = pack_h2(b.z, b.w);
    dst[i] = o;
}

// ---------------- router: 16 tokens/block, rw staged once (pitch 9) ---------
__global__ void router_k(const float* __restrict__ x,
                         const float* __restrict__ rw,
                         const float* __restrict__ rb) {
    __shared__ float srw[CC * 9];              // srw[c*9 + e], 36 KB
    __shared__ float simp[EE];
    __shared__ int   scnt[EE];
    __shared__ int   sbase[EE];
    __shared__ int   tok_e[16][2];
    __shared__ int   tok_lp[16][2];

    int tid  = threadIdx.x;
    int w    = tid >> 5;
    int lane = tid & 31;

    if (tid < EE) { simp[tid] = 0.f; scnt[tid] = 0; }
    for (int idx = tid; idx < CC * EE; idx += 256) {
        int c = idx >> 3, e = idx & 7;
        srw[c * 9 + e] = rw[idx];
    }
    __syncthreads();

#pragma unroll
    for (int t2 = 0; t2 < 2; t2++) {
        int slot = w * 2 + t2;
        int gw   = blockIdx.x * 16 + slot;
        const float* xr = x + (size_t)gw * CC;
        __half* xh = g_xh + (size_t)gw * CC;

        float acc[EE];
#pragma unroll
        for (int e = 0; e < EE; e++) acc[e] = 0.f;

#pragma unroll 4
        for (int i = 0; i < CC/32; i++) {
            int c = i*32 + lane;
            float xv = xr[c];
            xh[c] = __float2half_rn(xv);
            const float* wr = &srw[c * 9];
#pragma unroll
            for (int e = 0; e < EE; e++) acc[e] = fmaf(xv, wr[e], acc[e]);
        }
#pragma unroll
        for (int e = 0; e < EE; e++) {
#pragma unroll
            for (int off = 16; off; off >>= 1)
                acc[e] += __shfl_xor_sync(0xffffffffu, acc[e], off);
        }
        if (lane == 0) {
            float p[EE];
            float mx = -1e30f;
#pragma unroll
            for (int e = 0; e < EE; e++) { p[e] = acc[e] + rb[e]; mx = fmaxf(mx, p[e]); }
            float s = 0.f;
#pragma unroll
            for (int e = 0; e < EE; e++) { p[e] = expf(p[e] - mx); s += p[e]; }
            float inv = 1.f / s;
#pragma unroll
            for (int e = 0; e < EE; e++) p[e] *= inv;

            int i0 = 0;
#pragma unroll
            for (int e = 1; e < EE; e++) if (p[e] > p[i0]) i0 = e;
            int i1 = (i0 == 0) ? 1 : 0;
#pragma unroll
            for (int e = 0; e < EE; e++) if (e != i0 && p[e] > p[i1]) i1 = e;

            g_tv[gw*2]   = p[i0];
            g_tv[gw*2+1] = p[i1];
            int es[2] = { i0, i1 };
#pragma unroll
            for (int s2 = 0; s2 < 2; s2++) {
                int e = es[s2];
                tok_e[slot][s2]  = e;
                tok_lp[slot][s2] = atomicAdd(&scnt[e], 1);
            }
#pragma unroll
            for (int e = 0; e < EE; e++) atomicAdd(&simp[e], p[e]);
        }
    }
    __syncthreads();
    if (tid < EE) {
        sbase[tid] = atomicAdd(&g_cnt[tid], scnt[tid]);
        atomicAdd(&g_imp[tid], simp[tid]);
    }
    __syncthreads();
    if (tid < 32) {
        int wt = tid >> 1, s2 = tid & 1;
        int e   = tok_e[wt][s2];
        int pos = sbase[e] + tok_lp[wt][s2];
        int gt  = blockIdx.x * 16 + wt;
        if (pos < CAP) {
            g_rows[e*CAP + pos]  = gt;
            g_tokrow[gt*2 + s2]  = e*CAP + pos;
        } else {
            g_tokrow[gt*2 + s2]  = -1;
        }
    }
}

// ---------------- grouped GEMM, fp16 m16n8k16, 8 warps of 32x64 -------------
// MODE 1: h = relu(gather(xh) @ w1[e] + b1[e])  -> fp16 (g_hh)
// MODE 2: out[tok] += w_tok * (h @ w2[e] + b2[e])   (atomic combine)
template<int MODE>
__global__ __launch_bounds__(256, 2)
void gemm_k(const float* __restrict__ bias, float* __restrict__ out) {
    constexpr int  Kdim  = (MODE == 1) ? CC : HH;
    constexpr int  outN  = (MODE == 1) ? HH : CC;
    constexpr int  ITERS = Kdim / BK;

    const __half* A = (MODE == 1) ? g_xh : g_hh;
    const __half* W = (MODE == 1) ? g_w1h : g_w2h;

    int e   = blockIdx.z;
    int cnt = min(g_cnt[e], CAP);
    int m0  = blockIdx.y * BM;
    if (m0 >= cnt) return;
    int n0  = blockIdx.x * BN;

    extern __shared__ char smem[];
    __shared__ int arow[BM];

    int tid  = threadIdx.x;
    int lane = tid & 31, warp = tid >> 5;

    if (tid < BM) {
        int idx = m0 + tid;
        if (MODE == 1) arow[tid] = (idx < cnt) ? g_rows[e*CAP + idx] : 0;
        else           arow[tid] = (idx < cnt) ? g_rows[e*CAP + idx] : -1;
    }
    __syncthreads();

    // ---- cp.async descriptors ----
    int j  = tid & 7;
    int rT = tid >> 3;                 // 0..31
    uint32_t adst0 = (uint32_t)(rT*128 + ((j ^ (rT & 7)) << 4));
    const __half* Aj = A + j*8;
    int j2 = tid & 15;
    int rB = tid >> 4;                 // 0..15
    uint32_t bdst0 = (uint32_t)(A_BYTES + rB*256 + ((j2 ^ (rB & 7)) << 4));
    const __half* Bj = W + (size_t)e * Kdim * outN + n0 + j2*8;

    uint32_t smbase = (uint32_t)__cvta_generic_to_shared(smem);

    auto issue = [&](int stage, int it) {
        uint32_t s = smbase + (uint32_t)stage * STAGE_BYTES;
        size_t koff = (size_t)it * BK;
#pragma unroll
        for (int i = 0; i < 4; i++) {
            int r = rT + 32*i;
            size_t ar = (MODE == 1) ? (size_t)arow[r] : (size_t)(e*CAP + m0 + r);
            cp16(s + adst0 + (uint32_t)i*4096, Aj + ar * Kdim + koff);
        }
#pragma unroll
        for (int i = 0; i < 4; i++)
            cp16(s + bdst0 + (uint32_t)i*4096, Bj + (koff + (size_t)(rB + 16*i)) * outN);
    };

    issue(0, 0); cp_commit();
    issue(1, 1); cp_commit();

    // ---- ldmatrix per-lane components ----
    int wm  = (warp & 3) * 32;
    int wn  = (warp >> 2) * 64;
    int r16 = lane & 15;
    int coff = lane >> 4;
    int sl7  = lane & 7;
    uint32_t aoff0 = (uint32_t)((wm + r16) * 128);
    int sub = lane & 7;
    int mi  = lane >> 3;
    int kl  = ((mi >> 1) << 3) + sub;     // 0..15
    int slotbit = mi & 1;
    uint32_t bsl[4];
#pragma unroll
    for (int p = 0; p < 4; p++) {
        int slot = (wn >> 3) + 2*p + slotbit;
        bsl[p] = (uint32_t)(A_BYTES + kl*256 + ((slot ^ sub) << 4));
    }

    float acc[2][8][4];
#pragma unroll
    for (int mt = 0; mt < 2; mt++)
#pragma unroll
        for (int nt = 0; nt < 8; nt++)
#pragma unroll
            for (int q = 0; q < 4; q++) acc[mt][nt][q] = 0.f;

    for (int it = 0; it < ITERS; ++it) {
        cp_wait<1>();
        __syncthreads();
        if (it + 2 < ITERS) issue((it + 2) % STAGES, it + 2);
        cp_commit();

        uint32_t stg = smbase + (uint32_t)(it % STAGES) * STAGE_BYTES;

#pragma unroll
        for (int ks = 0; ks < BK; ks += 16) {
            const int c0 = (ks >> 3) + coff;
            const uint32_t csw = (uint32_t)((c0 ^ sl7) << 4);
            uint32_t af[2][4], bf[8][2];
#pragma unroll
            for (int mt = 0; mt < 2; mt++)
                ldsm4(af[mt][0], af[mt][1], af[mt][2], af[mt][3],
                      stg + aoff0 + (uint32_t)mt*2048 + csw);
#pragma unroll
            for (int p = 0; p < 4; p++)
                ldsm4t(bf[2*p][0], bf[2*p+1][0], bf[2*p][1], bf[2*p+1][1],
                       stg + bsl[p] + (uint32_t)(ks << 8));
#pragma unroll
            for (int mt = 0; mt < 2; mt++)
#pragma unroll
                for (int nt = 0; nt < 8; nt++) {
                    asm volatile(
                        "mma.sync.aligned.m16n8k16.row.col.f32.f16.f16.f32 "
                        "{%0,%1,%2,%3}, {%4,%5,%6,%7}, {%8,%9}, {%0,%1,%2,%3};"
                        : "+f"(acc[mt][nt][0]), "+f"(acc[mt][nt][1]),
                          "+f"(acc[mt][nt][2]), "+f"(acc[mt][nt][3])
                        : "r"(af[mt][0]), "r"(af[mt][1]), "r"(af[mt][2]), "r"(af[mt][3]),
                          "r"(bf[nt][0]), "r"(bf[nt][1]));
                }
        }
    }

    // ---- epilogue ----
    int q  = lane & 3;
    int gg = lane >> 2;
#pragma unroll
    for (int mt = 0; mt < 2; mt++) {
        int mrow = wm + mt*16 + gg;
        int t0 = arow[mrow], t1 = arow[mrow + 8];
        float w0 = 0.f, w1v = 0.f;
        if (MODE == 2) {
            w0  = (t0 >= 0) ? g_tv[t0] : 0.f;
            w1v = (t1 >= 0) ? g_tv[t1] : 0.f;
        }
#pragma unroll
        for (int nt = 0; nt < 8; nt++) {
            int col  = n0 + wn + nt*8 + 2*q;
            float bc0 = bias[e * outN + col];
            float bc1 = bias[e * outN + col + 1];
            float v00 = acc[mt][nt][0] + bc0;
            float v01 = acc[mt][nt][1] + bc1;
            float v10 = acc[mt][nt][2] + bc0;
            float v11 = acc[mt][nt][3] + bc1;
            if (MODE == 1) {
                size_t o0 = ((size_t)(e * CAP + m0 + mrow)) * outN + col;
                size_t o1 = o0 + (size_t)8 * outN;
                *(uint32_t*)(g_hh + o0) = pack_h2(fmaxf(v00, 0.f), fmaxf(v01, 0.f));
                *(uint32_t*)(g_hh + o1) = pack_h2(fmaxf(v10, 0.f), fmaxf(v11, 0.f));
            } else {
                if (t0 >= 0) {
                    float* p0 = out + (size_t)t0 * CC + col;
                    atomicAdd(p0,     w0 * v00);
                    atomicAdd(p0 + 1, w0 * v01);
                }
                if (t1 >= 0) {
                    float* p1 = out + (size_t)t1 * CC + col;
                    atomicAdd(p1,     w1v * v10);
                    atomicAdd(p1 + 1, w1v * v11);
                }
            }
        }
    }
}

// ---------------- aux loss ----------------
__global__ void aux_k(float* __restrict__ out, int out_size) {
    int lane = threadIdx.x;
    float v = 0.f;
    if (lane < EE)
        v = (g_imp[lane] / (float)NN) * ((float)g_cnt[lane] / (float)(NN * KKK));
#pragma unroll
    for (int off = 16; off; off >>= 1) v += __shfl_xor_sync(0xffffffffu, v, off);
    if (lane == 0) {
        if (out_size > NN * CC)     out[(size_t)NN * CC] = v;
        if (out_size - 1 > NN * CC) out[(size_t)out_size - 1] = v;
    }
}

// ---------------- launch ----------------
extern "C" void kernel_launch(void* const* d_in, const int* in_sizes, int n_in,
                              void* d_out, int out_size) {
    const float* x  = (const float*)d_in[0];
    const float* rw = (const float*)d_in[1];
    const float* rb = (const float*)d_in[2];
    const float* w1 = (const float*)d_in[3];
    const float* b1 = (const float*)d_in[4];
    const float* w2 = (const float*)d_in[5];
    const float* b2 = (const float*)d_in[6];
    float* out = (float*)d_out;

    static cudaStream_t s2 = nullptr;
    static cudaEvent_t evStart = nullptr, evW1 = nullptr, evW2 = nullptr;
    if (!s2) {
        cudaStreamCreateWithFlags(&s2, cudaStreamNonBlocking);
        cudaEventCreateWithFlags(&evStart, cudaEventDisableTiming);
        cudaEventCreateWithFlags(&evW1,   cudaEventDisableTiming);
        cudaEventCreateWithFlags(&evW2,   cudaEventDisableTiming);
    }

    cudaFuncSetAttribute(gemm_k<1>, cudaFuncAttributeMaxDynamicSharedMemorySize, SMEM_BYTES);
    cudaFuncSetAttribute(gemm_k<2>, cudaFuncAttributeMaxDynamicSharedMemorySize, SMEM_BYTES);

    __half* w1h; cudaGetSymbolAddress((void**)&w1h, g_w1h);
    __half* w2h; cudaGetSymbolAddress((void**)&w2h, g_w2h);

    // fork s2 off the (captured) main stream
    cudaEventRecord(evStart, 0);
    cudaStreamWaitEvent(s2, evStart, 0);

    // s2: weight conversions + output zeroing (overlaps router/gemm1)
    {
        int n8 = (int)((size_t)EE * CC * HH / 8);
        cvt_h<<<(n8 + 255) / 256, 256, 0, s2>>>((const float4*)w1, (uint4*)w1h, n8);
        cudaEventRecord(evW1, s2);
        cvt_h<<<(n8 + 255) / 256, 256, 0, s2>>>((const float4*)w2, (uint4*)w2h, n8);
        cudaMemsetAsync(d_out, 0, (size_t)out_size * sizeof(float), s2);
        cudaEventRecord(evW2, s2);
    }

    // main: router (+x->fp16)
    init_k<<<1, 32>>>();
    router_k<<<NN / 16, 256>>>(x, rw, rb);

    // gemm1 needs router + w1h
    cudaStreamWaitEvent(0, evW1, 0);
    gemm_k<1><<<dim3(HH / BN, YTILES, EE), 256, SMEM_BYTES>>>(b1, nullptr);
    // gemm2 additionally needs w2h + zeroed out
    cudaStreamWaitEvent(0, evW2, 0);
    aux_k<<<1, 32>>>(out, out_size);
    gemm_k<2><<<dim3(CC / BN, YTILES, EE), 256, SMEM_BYTES>>>(b2, out);
}